// round 1
// baseline (speedup 1.0000x reference)
#include <cuda_runtime.h>
#include <cuda_bf16.h>
#include <cstdint>

#define B_ 8192
#define D_ 2048
#define C_ 1000

#define EPS32 1.1920929e-7f

// ---------------- scratch (no allocations allowed) ----------------
__device__ __nv_bfloat16 g_z[B_ * (size_t)D_];   // z = feature + eps, bf16
__device__ __nv_bfloat16 g_w[C_ * (size_t)D_];   // cls_w, bf16 (same [C,K] layout)

// ---------------- kernel 1: z = feature + eps -> bf16 ----------------
__global__ void prep_z_kernel(const float4* __restrict__ f,
                              const float4* __restrict__ e,
                              float* __restrict__ loss_ptr) {
    int i = blockIdx.x * blockDim.x + threadIdx.x;          // one float4 per thread
    float4 a = f[i];
    float4 b = e[i];
    __nv_bfloat162 lo = __floats2bfloat162_rn(a.x + b.x, a.y + b.y);
    __nv_bfloat162 hi = __floats2bfloat162_rn(a.z + b.z, a.w + b.w);
    union { __nv_bfloat162 h[2]; uint2 u; } pk;
    pk.h[0] = lo; pk.h[1] = hi;
    reinterpret_cast<uint2*>(g_z)[i] = pk.u;
    if (i == 0 && loss_ptr) *loss_ptr = 0.0f;
}

// ---------------- kernel 2: cls_w -> bf16 ----------------
__global__ void prep_w_kernel(const float4* __restrict__ w) {
    int i = blockIdx.x * blockDim.x + threadIdx.x;
    float4 a = w[i];
    __nv_bfloat162 lo = __floats2bfloat162_rn(a.x, a.y);
    __nv_bfloat162 hi = __floats2bfloat162_rn(a.z, a.w);
    union { __nv_bfloat162 h[2]; uint2 u; } pk;
    pk.h[0] = lo; pk.h[1] = hi;
    reinterpret_cast<uint2*>(g_w)[i] = pk.u;
}

// ---------------- kernel 3: GEMM raw = z @ w^T + cls_b ----------------
// CTA tile 128(M) x 128(N) x 32(K). 256 threads = 8 warps, warp grid 4x2,
// warp tile 32x64, mma.sync m16n8k16 bf16 -> fp32.
#define BM 128
#define BN 128
#define BK 32
#define SK 40   // padded smem row stride (conflict-free for b32 LDS pattern)

__device__ __forceinline__ void mma16816(float c[4], const uint32_t a[4],
                                         uint32_t b0, uint32_t b1) {
    asm volatile(
        "mma.sync.aligned.m16n8k16.row.col.f32.bf16.bf16.f32 "
        "{%0,%1,%2,%3}, {%4,%5,%6,%7}, {%8,%9}, {%0,%1,%2,%3};\n"
        : "+f"(c[0]), "+f"(c[1]), "+f"(c[2]), "+f"(c[3])
        : "r"(a[0]), "r"(a[1]), "r"(a[2]), "r"(a[3]), "r"(b0), "r"(b1));
}

__global__ __launch_bounds__(256, 2) void gemm_kernel(
    const float* __restrict__ cls_b, float* __restrict__ raw) {
    __shared__ __nv_bfloat16 As[BM][SK];
    __shared__ __nv_bfloat16 Bs[BN][SK];

    const int tid  = threadIdx.x;
    const int warp = tid >> 5;
    const int lane = tid & 31;
    const int wm   = warp >> 1;   // 0..3
    const int wn   = warp & 1;    // 0..1
    const int g    = lane >> 2;   // 0..7
    const int tg   = lane & 3;    // 0..3

    const int m0 = blockIdx.y * BM;
    const int n0 = blockIdx.x * BN;

    float acc[2][8][4];
#pragma unroll
    for (int mi = 0; mi < 2; mi++)
#pragma unroll
        for (int ni = 0; ni < 8; ni++)
#pragma unroll
            for (int r = 0; r < 4; r++) acc[mi][ni][r] = 0.0f;

    // global->smem load pattern: 16B per thread, 2 rows per array
    const int lrow = tid >> 2;          // 0..63
    const int lcol = (tid & 3) * 8;     // 0,8,16,24

    for (int k0 = 0; k0 < D_; k0 += BK) {
        // A tile (M=8192 divisible by 128 -> no guard)
        *reinterpret_cast<uint4*>(&As[lrow][lcol]) =
            *reinterpret_cast<const uint4*>(&g_z[(size_t)(m0 + lrow) * D_ + k0 + lcol]);
        *reinterpret_cast<uint4*>(&As[lrow + 64][lcol]) =
            *reinterpret_cast<const uint4*>(&g_z[(size_t)(m0 + lrow + 64) * D_ + k0 + lcol]);
        // B tile with N-edge guard (C_=1000)
        uint4 bz = make_uint4(0u, 0u, 0u, 0u);
        int nr = n0 + lrow;
        uint4 bv = bz;
        if (nr < C_) bv = *reinterpret_cast<const uint4*>(&g_w[(size_t)nr * D_ + k0 + lcol]);
        *reinterpret_cast<uint4*>(&Bs[lrow][lcol]) = bv;
        nr = n0 + lrow + 64;
        bv = bz;
        if (nr < C_) bv = *reinterpret_cast<const uint4*>(&g_w[(size_t)nr * D_ + k0 + lcol]);
        *reinterpret_cast<uint4*>(&Bs[lrow + 64][lcol]) = bv;

        __syncthreads();

#pragma unroll
        for (int kk = 0; kk < 2; kk++) {
            const int kc = kk * 16 + tg * 2;
            uint32_t a[2][4];
#pragma unroll
            for (int mi = 0; mi < 2; mi++) {
                const int rb = wm * 32 + mi * 16;
                a[mi][0] = *reinterpret_cast<const uint32_t*>(&As[rb + g][kc]);
                a[mi][1] = *reinterpret_cast<const uint32_t*>(&As[rb + g + 8][kc]);
                a[mi][2] = *reinterpret_cast<const uint32_t*>(&As[rb + g][kc + 8]);
                a[mi][3] = *reinterpret_cast<const uint32_t*>(&As[rb + g + 8][kc + 8]);
            }
#pragma unroll
            for (int ni = 0; ni < 8; ni++) {
                const int nb = wn * 64 + ni * 8 + g;
                uint32_t b0 = *reinterpret_cast<const uint32_t*>(&Bs[nb][kc]);
                uint32_t b1 = *reinterpret_cast<const uint32_t*>(&Bs[nb][kc + 8]);
                mma16816(acc[0][ni], a[0], b0, b1);
                mma16816(acc[1][ni], a[1], b0, b1);
            }
        }
        __syncthreads();
    }

    // epilogue: + cls_b, store raw probs into d_out
#pragma unroll
    for (int mi = 0; mi < 2; mi++) {
#pragma unroll
        for (int ni = 0; ni < 8; ni++) {
            const int row = m0 + wm * 32 + mi * 16 + g;
            const int col = n0 + wn * 64 + ni * 8 + tg * 2;
            if (col < C_) {
                float bb0 = cls_b[col];
                float bb1 = (col + 1 < C_) ? cls_b[col + 1] : 0.0f;
                float* o = raw + (size_t)row * C_ + col;
                o[0] = acc[mi][ni][0] + bb0;
                if (col + 1 < C_) o[1] = acc[mi][ni][1] + bb1;
                o += 8 * (size_t)C_;
                o[0] = acc[mi][ni][2] + bb0;
                if (col + 1 < C_) o[1] = acc[mi][ni][3] + bb1;
            }
        }
    }
}

// ---------------- kernel 4: per-row normalize/log + loss ----------------
__global__ void epilogue_kernel(float* __restrict__ out,
                                const int* __restrict__ target,
                                float* __restrict__ loss_ptr) {
    const int b = blockIdx.x;
    const int tid = threadIdx.x;
    float* row = out + (size_t)b * C_;

    float s = 0.0f;
    for (int i = tid; i < C_; i += 256) s += row[i];
#pragma unroll
    for (int o = 16; o > 0; o >>= 1) s += __shfl_xor_sync(0xffffffffu, s, o);

    __shared__ float red[8];
    __shared__ float tot;
    if ((tid & 31) == 0) red[tid >> 5] = s;
    __syncthreads();
    if (tid == 0) {
        float t = 0.0f;
#pragma unroll
        for (int i = 0; i < 8; i++) t += red[i];
        tot = t;
    }
    __syncthreads();

    const float inv = 1.0f / tot;
    const int tgt = target[b];
    for (int i = tid; i < C_; i += 256) {
        float p = row[i] * inv;
        p = fminf(fmaxf(p, EPS32), 1.0f - EPS32);
        float lg = logf(p);
        row[i] = lg;
        if (i == tgt && loss_ptr) {
            // loss = mean(gamma*rex + h3); gamma*rex ~ 1e-40 is exactly absorbed
            // by h3 ~ 6.9 in fp32, so loss == mean(-logits[b, target[b]]).
            atomicAdd(loss_ptr, -lg * (1.0f / (float)B_));
        }
    }
}

// ---------------- launch ----------------
extern "C" void kernel_launch(void* const* d_in, const int* in_sizes, int n_in,
                              void* d_out, int out_size) {
    const float* feature = (const float*)d_in[0];
    // d_in[1] = y_w, d_in[2] = y_b : unused (gamma*rex term vanishes in fp32)
    const float* cls_w   = (const float*)d_in[3];
    const float* cls_b   = (const float*)d_in[4];
    const float* eps     = (const float*)d_in[5];
    const int*   target  = (const int*)d_in[6];

    float* out = (float*)d_out;
    float* loss_ptr = (out_size >= B_ * C_ + 1) ? (out + (size_t)B_ * C_) : nullptr;

    // 1) z = feature + eps -> bf16 ; zero loss accumulator
    prep_z_kernel<<<(B_ * D_ / 4) / 256, 256>>>(
        (const float4*)feature, (const float4*)eps, loss_ptr);

    // 2) cls_w -> bf16
    prep_w_kernel<<<(C_ * D_ / 4) / 256, 256>>>((const float4*)cls_w);

    // 3) raw = z @ cls_w^T + cls_b  (written into d_out)
    dim3 grid((C_ + BN - 1) / BN, B_ / BM);   // 8 x 64
    gemm_kernel<<<grid, 256>>>(cls_b, out);

    // 4) logits = log(clamp(raw / rowsum)), loss = mean(-logits[b, target])
    epilogue_kernel<<<B_, 256>>>(out, target, loss_ptr);
}

// round 3
// speedup vs baseline: 1.6421x; 1.6421x over previous
#include <cuda_runtime.h>
#include <cuda_bf16.h>
#include <cstdint>

#define B_ 8192
#define D_ 2048
#define C_ 1000
#define EPS32 1.1920929e-7f

// ---------------- scratch (no allocations allowed) ----------------
__device__ __nv_bfloat16 g_z[B_ * (size_t)D_];   // z = feature + eps, bf16
__device__ __nv_bfloat16 g_w[C_ * (size_t)D_];   // cls_w, bf16 [C, D] K-major

// ---------------- kernel 1: z = feature + eps -> bf16 ----------------
__global__ void prep_z_kernel(const float4* __restrict__ f,
                              const float4* __restrict__ e,
                              float* __restrict__ loss_ptr) {
    int i = blockIdx.x * blockDim.x + threadIdx.x;
    float4 a = f[i];
    float4 b = e[i];
    __nv_bfloat162 lo = __floats2bfloat162_rn(a.x + b.x, a.y + b.y);
    __nv_bfloat162 hi = __floats2bfloat162_rn(a.z + b.z, a.w + b.w);
    union { __nv_bfloat162 h[2]; uint2 u; } pk;
    pk.h[0] = lo; pk.h[1] = hi;
    reinterpret_cast<uint2*>(g_z)[i] = pk.u;
    if (i == 0 && loss_ptr) *loss_ptr = 0.0f;
}

// ---------------- kernel 2: cls_w -> bf16 ----------------
__global__ void prep_w_kernel(const float4* __restrict__ w) {
    int i = blockIdx.x * blockDim.x + threadIdx.x;
    float4 a = w[i];
    __nv_bfloat162 lo = __floats2bfloat162_rn(a.x, a.y);
    __nv_bfloat162 hi = __floats2bfloat162_rn(a.z, a.w);
    union { __nv_bfloat162 h[2]; uint2 u; } pk;
    pk.h[0] = lo; pk.h[1] = hi;
    reinterpret_cast<uint2*>(g_w)[i] = pk.u;
}

// ============================================================================
// GEMM raw = z @ w^T + cls_b : HMMA (mma.sync) + ldmatrix + cp.async pipeline
// CTA tile 128x128, BK=32, 4 stages. 256 threads = 8 warps (4m x 2n),
// warp tile 32(M) x 64(N). SMEM rows are 64B (K=32 bf16), SW64 swizzled.
// ============================================================================
#define BM 128
#define BN 128
#define BK 32
#define STAGES 4
#define NIT (D_ / BK)
#define STAGE_BYTES 16384           // A: 128*64 = 8192, B: 8192
#define SMEM_TOTAL (STAGES * STAGE_BYTES)

#define SWZ64(o) ((o) ^ (((o) >> 3) & 0x30))

__device__ __forceinline__ uint32_t smem_u32(const void* p) {
    uint32_t a;
    asm("{ .reg .u64 t; cvta.to.shared.u64 t, %1; cvt.u32.u64 %0, t; }"
        : "=r"(a) : "l"(p));
    return a;
}
__device__ __forceinline__ void ldsm_x4(uint32_t r[4], uint32_t a) {
    asm volatile("ldmatrix.sync.aligned.m8n8.x4.shared.b16 {%0,%1,%2,%3}, [%4];"
                 : "=r"(r[0]), "=r"(r[1]), "=r"(r[2]), "=r"(r[3]) : "r"(a));
}
__device__ __forceinline__ void ldsm_x2(uint32_t r[2], uint32_t a) {
    asm volatile("ldmatrix.sync.aligned.m8n8.x2.shared.b16 {%0,%1}, [%2];"
                 : "=r"(r[0]), "=r"(r[1]) : "r"(a));
}
__device__ __forceinline__ void cpasync16(uint32_t dst, const void* src,
                                          uint32_t srcsz) {
    asm volatile("cp.async.cg.shared.global [%0], [%1], 16, %2;"
                 :: "r"(dst), "l"(src), "r"(srcsz));
}
__device__ __forceinline__ void mma16816(float c[4], const uint32_t a[4],
                                         uint32_t b0, uint32_t b1) {
    asm volatile(
        "mma.sync.aligned.m16n8k16.row.col.f32.bf16.bf16.f32 "
        "{%0,%1,%2,%3}, {%4,%5,%6,%7}, {%8,%9}, {%0,%1,%2,%3};\n"
        : "+f"(c[0]), "+f"(c[1]), "+f"(c[2]), "+f"(c[3])
        : "r"(a[0]), "r"(a[1]), "r"(a[2]), "r"(a[3]), "r"(b0), "r"(b1));
}

__global__ __launch_bounds__(256, 2) void gemm_kernel(
    const float* __restrict__ cls_b, float* __restrict__ raw) {
    extern __shared__ char smem[];
    const uint32_t sb = smem_u32(smem);
    const int tid  = threadIdx.x;
    const int warp = tid >> 5;
    const int lane = tid & 31;
    const int wm   = warp >> 1;   // 0..3
    const int wn   = warp & 1;    // 0..1
    const int m0   = blockIdx.y * BM;
    const int n0   = blockIdx.x * BN;

    // ---- cp.async thread mapping: row = tid>>2 (and +64), chunk = tid&3 ----
    const int arow = tid >> 2;
    const int achk = tid & 3;
    const __nv_bfloat16* asrc0 = &g_z[(size_t)(m0 + arow) * D_ + achk * 8];
    const __nv_bfloat16* asrc1 = asrc0 + (size_t)64 * D_;
    const uint32_t adst0 = sb + SWZ64(arow * 64 + achk * 16);
    const uint32_t adst1 = sb + SWZ64((arow + 64) * 64 + achk * 16);

    const int brow0 = arow, brow1 = arow + 64;
    const uint32_t bsz0 = (n0 + brow0 < C_) ? 16u : 0u;
    const uint32_t bsz1 = (n0 + brow1 < C_) ? 16u : 0u;
    const int br0c = (n0 + brow0 < C_) ? (n0 + brow0) : (C_ - 1);
    const int br1c = (n0 + brow1 < C_) ? (n0 + brow1) : (C_ - 1);
    const __nv_bfloat16* bsrc0 = &g_w[(size_t)br0c * D_ + achk * 8];
    const __nv_bfloat16* bsrc1 = &g_w[(size_t)br1c * D_ + achk * 8];
    const uint32_t bdst0 = sb + 8192 + SWZ64(brow0 * 64 + achk * 16);
    const uint32_t bdst1 = sb + 8192 + SWZ64(brow1 * 64 + achk * 16);

    // ---- ldmatrix per-lane offsets (within a stage) ----
    const int l15 = lane & 15;
    uint32_t aoff[2], boff[2];
#pragma unroll
    for (int kk = 0; kk < 2; kk++) {
        const int archunk = kk * 2 + (lane >> 4);
        aoff[kk] = SWZ64((wm * 32 + l15) * 64 + archunk * 16);
        const int bchunk = kk * 2 + ((l15 >> 3) & 1);
        boff[kk] = 8192 + SWZ64((wn * 64 + (l15 & 7)) * 64 + bchunk * 16);
    }

    float acc[2][8][4];
#pragma unroll
    for (int mi = 0; mi < 2; mi++)
#pragma unroll
        for (int ni = 0; ni < 8; ni++)
#pragma unroll
            for (int r = 0; r < 4; r++) acc[mi][ni][r] = 0.0f;

    // ---- prologue: 3 stages in flight ----
#pragma unroll
    for (int s = 0; s < STAGES - 1; s++) {
        const uint32_t so = s * STAGE_BYTES;
        const int ko = s * BK * 2;           // byte-ish offset in elements: s*BK
        cpasync16(adst0 + so, asrc0 + s * BK, 16u);
        cpasync16(adst1 + so, asrc1 + s * BK, 16u);
        cpasync16(bdst0 + so, bsrc0 + s * BK, bsz0);
        cpasync16(bdst1 + so, bsrc1 + s * BK, bsz1);
        asm volatile("cp.async.commit_group;" ::: "memory");
        (void)ko;
    }

    for (int it = 0; it < NIT; it++) {
        asm volatile("cp.async.wait_group 2;" ::: "memory");
        __syncthreads();

        // issue next stage load (buffer (it+3)&3) — safe: barrier above ensures
        // every warp finished compute of iter it-1 which used this buffer.
        if (it + STAGES - 1 < NIT) {
            const int s = (it + STAGES - 1) & 3;
            const uint32_t so = s * STAGE_BYTES;
            const int k0 = (it + STAGES - 1) * BK;
            cpasync16(adst0 + so, asrc0 + k0, 16u);
            cpasync16(adst1 + so, asrc1 + k0, 16u);
            cpasync16(bdst0 + so, bsrc0 + k0, bsz0);
            cpasync16(bdst1 + so, bsrc1 + k0, bsz1);
        }
        asm volatile("cp.async.commit_group;" ::: "memory");

        // ---- compute on buffer it&3 ----
        const uint32_t base = sb + (it & 3) * STAGE_BYTES;
#pragma unroll
        for (int kk = 0; kk < 2; kk++) {
            uint32_t A0[4], A1[4];
            ldsm_x4(A0, base + aoff[kk]);
            ldsm_x4(A1, base + aoff[kk] + 1024);   // +16 rows
            uint32_t Bf[8][2];
#pragma unroll
            for (int ni = 0; ni < 8; ni++)
                ldsm_x2(Bf[ni], base + boff[kk] + ni * 512);  // +8 n-rows
#pragma unroll
            for (int ni = 0; ni < 8; ni++) {
                mma16816(acc[0][ni], A0, Bf[ni][0], Bf[ni][1]);
                mma16816(acc[1][ni], A1, Bf[ni][0], Bf[ni][1]);
            }
        }
    }

    // ---- store: + cls_b, raw probs into d_out ----
    const int g  = lane >> 2;
    const int tg = lane & 3;
#pragma unroll
    for (int mi = 0; mi < 2; mi++) {
#pragma unroll
        for (int ni = 0; ni < 8; ni++) {
            const int row = m0 + wm * 32 + mi * 16 + g;
            const int col = n0 + wn * 64 + ni * 8 + tg * 2;
            if (col < C_) {   // C_ even -> col+1 < C_ too
                const float2 bb = *reinterpret_cast<const float2*>(cls_b + col);
                float2 o0, o1;
                o0.x = acc[mi][ni][0] + bb.x;
                o0.y = acc[mi][ni][1] + bb.y;
                o1.x = acc[mi][ni][2] + bb.x;
                o1.y = acc[mi][ni][3] + bb.y;
                *reinterpret_cast<float2*>(raw + (size_t)row * C_ + col) = o0;
                *reinterpret_cast<float2*>(raw + (size_t)(row + 8) * C_ + col) = o1;
            }
        }
    }
}

// ---------------- kernel 4: per-row normalize/log + loss --------------------
// one warp per row; values held in registers; warp-only reduction
__global__ __launch_bounds__(256) void epilogue_kernel(
    float* __restrict__ out, const int* __restrict__ target,
    float* __restrict__ loss_ptr) {
    const int wid  = threadIdx.x >> 5;
    const int lane = threadIdx.x & 31;
    const int row  = blockIdx.x * 8 + wid;
    float* r = out + (size_t)row * C_;

    float4 v[8];
    float s = 0.0f;
#pragma unroll
    for (int j = 0; j < 8; j++) {
        const int idx = lane + j * 32;            // float4 index, 250 valid
        if (idx < 250) {
            v[j] = *reinterpret_cast<const float4*>(r + idx * 4);
            s += (v[j].x + v[j].y) + (v[j].z + v[j].w);
        }
    }
#pragma unroll
    for (int o = 16; o > 0; o >>= 1) s += __shfl_xor_sync(0xffffffffu, s, o);

    const float inv = 1.0f / s;
    const int tgt = target[row];
#pragma unroll
    for (int j = 0; j < 8; j++) {
        const int idx = lane + j * 32;
        if (idx < 250) {
            float4 lg;
            float p;
            p = fminf(fmaxf(v[j].x * inv, EPS32), 1.0f - EPS32); lg.x = __logf(p);
            p = fminf(fmaxf(v[j].y * inv, EPS32), 1.0f - EPS32); lg.y = __logf(p);
            p = fminf(fmaxf(v[j].z * inv, EPS32), 1.0f - EPS32); lg.z = __logf(p);
            p = fminf(fmaxf(v[j].w * inv, EPS32), 1.0f - EPS32); lg.w = __logf(p);
            *reinterpret_cast<float4*>(r + idx * 4) = lg;
            const int base = idx * 4;
            if (loss_ptr && tgt >= base && tgt < base + 4) {
                const float l = (tgt == base) ? lg.x : (tgt == base + 1) ? lg.y
                              : (tgt == base + 2) ? lg.z : lg.w;
                // loss = mean(gamma*rex + h3); gamma ~ 3.7e-44 makes gamma*rex
                // (~1e-40) vanish when added to h3 ~ 6.9 in fp32, so
                // loss == mean(-logits[b, target[b]]).
                atomicAdd(loss_ptr, -l * (1.0f / (float)B_));
            }
        }
    }
}

// ---------------- launch ----------------
extern "C" void kernel_launch(void* const* d_in, const int* in_sizes, int n_in,
                              void* d_out, int out_size) {
    const float* feature = (const float*)d_in[0];
    // d_in[1] = y_w, d_in[2] = y_b : unused (gamma*rex term vanishes in fp32)
    const float* cls_w   = (const float*)d_in[3];
    const float* cls_b   = (const float*)d_in[4];
    const float* eps     = (const float*)d_in[5];
    const int*   target  = (const int*)d_in[6];

    float* out = (float*)d_out;
    float* loss_ptr = (out_size >= B_ * C_ + 1) ? (out + (size_t)B_ * C_) : nullptr;

    static bool attr_set = false;
    if (!attr_set) {
        cudaFuncSetAttribute(gemm_kernel,
                             cudaFuncAttributeMaxDynamicSharedMemorySize,
                             SMEM_TOTAL);
        attr_set = true;
    }

    // 1) z = feature + eps -> bf16 ; zero loss accumulator
    prep_z_kernel<<<(B_ * D_ / 4) / 256, 256>>>(
        (const float4*)feature, (const float4*)eps, loss_ptr);

    // 2) cls_w -> bf16
    prep_w_kernel<<<(C_ * D_ / 4) / 256, 256>>>((const float4*)cls_w);

    // 3) raw = z @ cls_w^T + cls_b (written into d_out)
    dim3 grid((C_ + BN - 1) / BN, B_ / BM);   // 8 x 64 = 512 CTAs
    gemm_kernel<<<grid, 256, SMEM_TOTAL>>>(cls_b, out);

    // 4) logits = log(clamp(raw / rowsum)), loss = mean(-logits[b, target])
    epilogue_kernel<<<B_ / 8, 256>>>(out, target, loss_ptr);
}